// round 11
// baseline (speedup 1.0000x reference)
#include <cuda_runtime.h>
#include <cstdint>

// Problem constants (from reference)
#define E_NUM 128
#define R_NUM 65536
#define S_NUM 100000
#define ER (E_NUM * R_NUM)          // 8,388,608 floats per table

// Interleaved scratch accumulator: scratch[2*(e*R+r)+0] = delta-a,
//                                  scratch[2*(e*R+r)+1] = delta-b
// 2*ER floats = 64 MiB, static device global (no allocation).
//
// INVARIANT: g_scratch is all-zero at entry to every kernel_launch call.
//  - call #1: CUDA zero-initializes __device__ globals at module load.
//  - every call: after merge quarter Q consumes scratch quarter Q, a memset
//    node refills it with zeros (pipelined on a side stream, hidden under the
//    remaining merge quarters). Every call does identical work.
__device__ float g_scratch[2u * ER];

// ---------------------------------------------------------------------------
// Kernel 1: scatter-add (MONOLITHIC — splitting pays ~4-5us RED-drain per
// piece, measured R6/R9). One thread per 4 (sample, estimator) pairs; int4 sr
// load covers e..e+3 of one sample; da/db broadcast. 4x red.global.add.v2.f32.
// 12.8M RED lanes at the 1.29 cyc/lane SM-LSU spread-REDG floor: 62us.
// ---------------------------------------------------------------------------
__global__ void __launch_bounds__(256) scatter_v2x4_kernel(
        const int4* __restrict__ sr4,
        const float* __restrict__ da,
        const float* __restrict__ db) {
    int t = blockIdx.x * blockDim.x + threadIdx.x;   // [0, S*E/4) exact grid
    int e0 = (t & 31) << 2;                          // e = e0..e0+3
    int s  = t >> 5;                                 // warp-uniform
    int4 r = __ldg(sr4 + t);                         // coalesced 16B
    float va = __ldg(da + s);                        // broadcast
    float vb = __ldg(db + s);

    float* base = g_scratch + 2u * (size_t)e0 * R_NUM;
    float* p0 = base + 2u * (size_t)r.x;
    float* p1 = base + 2u * ((size_t)R_NUM + (size_t)r.y);
    float* p2 = base + 2u * (2u * (size_t)R_NUM + (size_t)r.z);
    float* p3 = base + 2u * (3u * (size_t)R_NUM + (size_t)r.w);
    asm volatile("red.global.add.v2.f32 [%0], {%1, %2};" :: "l"(p0), "f"(va), "f"(vb) : "memory");
    asm volatile("red.global.add.v2.f32 [%0], {%1, %2};" :: "l"(p1), "f"(va), "f"(vb) : "memory");
    asm volatile("red.global.add.v2.f32 [%0], {%1, %2};" :: "l"(p2), "f"(va), "f"(vb) : "memory");
    asm volatile("red.global.add.v2.f32 [%0], {%1, %2};" :: "l"(p3), "f"(va), "f"(vb) : "memory");
}

// ---------------------------------------------------------------------------
// Merge quarter Q (e in [32Q, 32Q+32)): out[0][q] = a + scratch.a,
// out[1][q] = b + scratch.b (deinterleave). Merge splits cleanly (R6 data:
// no drain penalty, unlike scatter). scratch L2-warm; a/b cold -> __ldcs;
// out -> __stcs.
// ---------------------------------------------------------------------------
template <int Q>
__global__ void __launch_bounds__(256) merge_q_kernel(
        const float4* __restrict__ a,
        const float4* __restrict__ b,
        float4* __restrict__ out) {
    int i = blockIdx.x * blockDim.x + threadIdx.x;   // [0, ER/16) exact grid
    int gi = Q * (ER / 16) + i;                      // float4 idx within table
    const float4* s4 = reinterpret_cast<const float4*>(g_scratch);
    float4 p0 = s4[2 * gi + 0];  // {a0,b0,a1,b1}
    float4 p1 = s4[2 * gi + 1];  // {a2,b2,a3,b3}
    float4 va = __ldcs(a + gi);
    float4 vb = __ldcs(b + gi);
    __stcs(out + gi,
           make_float4(va.x + p0.x, va.y + p0.z, va.z + p1.x, va.w + p1.z));
    __stcs(out + ER / 4 + gi,
           make_float4(vb.x + p0.y, vb.y + p0.w, vb.z + p1.y, vb.w + p1.w));
}

extern "C" void kernel_launch(void* const* d_in, const int* in_sizes, int n_in,
                              void* d_out, int out_size) {
    const float* a  = (const float*)d_in[0];          // [E, R]
    const float* b  = (const float*)d_in[1];          // [E, R]
    const int*   sr = (const int*)d_in[2];            // [S, E]
    const float* da = (const float*)d_in[3];          // [S]
    const float* db = (const float*)d_in[4];          // [S]
    float* out = (float*)d_out;                       // [2, E, R]

    // One-time host-side resources (no device memory allocated).
    static char* sp = [] {
        void* p = nullptr;
        cudaGetSymbolAddress(&p, g_scratch);
        return (char*)p;
    }();
    static cudaStream_t s2 = [] {
        cudaStream_t s; cudaStreamCreateWithFlags(&s, cudaStreamNonBlocking);
        return s;
    }();
    static cudaEvent_t evm[4] = {};
    static cudaEvent_t evf = [] {
        for (int i = 0; i < 4; i++)
            cudaEventCreateWithFlags(&evm[i], cudaEventDisableTiming);
        cudaEvent_t e; cudaEventCreateWithFlags(&e, cudaEventDisableTiming);
        return e;
    }();

    const size_t QBYTES = sizeof(float) * 2u * ER / 4;   // 16 MiB scratch/quarter
    const int SC_BLOCKS = S_NUM * E_NUM / 4 / 256;        // 12500 exact
    const int MQ_BLOCKS = ER / 16 / 256;                  // 2048 exact

    // Phase 1: monolithic scatter into zeroed scratch (invariant at entry).
    scatter_v2x4_kernel<<<SC_BLOCKS, 256>>>((const int4*)sr, da, db);

    // Phase 2: merge quarters on main stream; after each quarter's scratch is
    // consumed, a side-stream memset refills it with zeros (hidden under the
    // remaining merge quarters). Side stream forks legally via event waits.
    merge_q_kernel<0><<<MQ_BLOCKS, 256>>>((const float4*)a, (const float4*)b, (float4*)out);
    cudaEventRecord(evm[0], 0);
    cudaStreamWaitEvent(s2, evm[0], 0);
    cudaMemsetAsync(sp + 0 * QBYTES, 0, QBYTES, s2);

    merge_q_kernel<1><<<MQ_BLOCKS, 256>>>((const float4*)a, (const float4*)b, (float4*)out);
    cudaEventRecord(evm[1], 0);
    cudaStreamWaitEvent(s2, evm[1], 0);
    cudaMemsetAsync(sp + 1 * QBYTES, 0, QBYTES, s2);

    merge_q_kernel<2><<<MQ_BLOCKS, 256>>>((const float4*)a, (const float4*)b, (float4*)out);
    cudaEventRecord(evm[2], 0);
    cudaStreamWaitEvent(s2, evm[2], 0);
    cudaMemsetAsync(sp + 2 * QBYTES, 0, QBYTES, s2);

    merge_q_kernel<3><<<MQ_BLOCKS, 256>>>((const float4*)a, (const float4*)b, (float4*)out);
    cudaEventRecord(evm[3], 0);
    cudaStreamWaitEvent(s2, evm[3], 0);
    cudaMemsetAsync(sp + 3 * QBYTES, 0, QBYTES, s2);
    cudaEventRecord(evf, s2);

    // Join: graph completes when the last fill is done (restores invariant).
    cudaStreamWaitEvent(0, evf, 0);
}

// round 12
// speedup vs baseline: 1.1246x; 1.1246x over previous
#include <cuda_runtime.h>
#include <cstdint>

// Problem constants (from reference)
#define E_NUM 128
#define R_NUM 65536
#define S_NUM 100000
#define ER (E_NUM * R_NUM)          // 8,388,608 floats per table

// Interleaved scratch accumulator: scratch[2*(e*R+r)+0] = delta-a,
//                                  scratch[2*(e*R+r)+1] = delta-b
// 2*ER floats = 64 MiB, static device global (no allocation).
__device__ float g_scratch[2u * ER];

// ---------------------------------------------------------------------------
// Kernel 1: TMA bulk-store fill. Each CTA zeroes a 32KB SMEM staging buffer
// (SMEM-port stores, not the global ST path), then issues ONE
// cp.async.bulk SMEM->GMEM (UTMASTG) for its 32KB slice. The TMA store path
// is LTS-cap path-independent (~6300 B/cyc) vs ~3500 B/cyc for plain STG,
// so this should fill 64 MiB in ~6us instead of 12.4.
// ---------------------------------------------------------------------------
#define FILL_CHUNK 32768
__global__ void __launch_bounds__(128) tma_fill_kernel(char* __restrict__ dst) {
    __shared__ __align__(128) char buf[FILL_CHUNK];
    float4* b4 = reinterpret_cast<float4*>(buf);
    const float4 z = make_float4(0.f, 0.f, 0.f, 0.f);
    #pragma unroll
    for (int i = threadIdx.x; i < FILL_CHUNK / 16; i += 128) b4[i] = z;
    __syncthreads();
    if (threadIdx.x == 0) {
        asm volatile("fence.proxy.async.shared::cta;" ::: "memory");
        uint32_t saddr = (uint32_t)__cvta_generic_to_shared(buf);
        char* g = dst + (size_t)blockIdx.x * FILL_CHUNK;
        asm volatile(
            "cp.async.bulk.global.shared::cta.bulk_group [%0], [%1], %2;"
            :: "l"(g), "r"(saddr), "n"(FILL_CHUNK) : "memory");
        asm volatile("cp.async.bulk.commit_group;" ::: "memory");
        asm volatile("cp.async.bulk.wait_group 0;" ::: "memory");
    }
}

// ---------------------------------------------------------------------------
// Kernel 2: scatter-add (MONOLITHIC — splitting pays ~4-5us RED-drain per
// piece, R6/R9). One thread per 4 (sample, estimator) pairs; int4 sr load
// covers e..e+3 of one sample; da/db broadcast. 4x red.global.add.v2.f32.
// 12.8M RED lanes at the 1.29 cyc/lane SM-LSU spread-REDG floor: 62us.
// ---------------------------------------------------------------------------
__global__ void __launch_bounds__(256) scatter_v2x4_kernel(
        const int4* __restrict__ sr4,
        const float* __restrict__ da,
        const float* __restrict__ db) {
    int t = blockIdx.x * blockDim.x + threadIdx.x;   // [0, S*E/4) exact grid
    int e0 = (t & 31) << 2;                          // e = e0..e0+3
    int s  = t >> 5;                                 // warp-uniform
    int4 r = __ldg(sr4 + t);                         // coalesced 16B
    float va = __ldg(da + s);                        // broadcast
    float vb = __ldg(db + s);

    float* base = g_scratch + 2u * (size_t)e0 * R_NUM;
    float* p0 = base + 2u * (size_t)r.x;
    float* p1 = base + 2u * ((size_t)R_NUM + (size_t)r.y);
    float* p2 = base + 2u * (2u * (size_t)R_NUM + (size_t)r.z);
    float* p3 = base + 2u * (3u * (size_t)R_NUM + (size_t)r.w);
    asm volatile("red.global.add.v2.f32 [%0], {%1, %2};" :: "l"(p0), "f"(va), "f"(vb) : "memory");
    asm volatile("red.global.add.v2.f32 [%0], {%1, %2};" :: "l"(p1), "f"(va), "f"(vb) : "memory");
    asm volatile("red.global.add.v2.f32 [%0], {%1, %2};" :: "l"(p2), "f"(va), "f"(vb) : "memory");
    asm volatile("red.global.add.v2.f32 [%0], {%1, %2};" :: "l"(p3), "f"(va), "f"(vb) : "memory");
}

// ---------------------------------------------------------------------------
// Kernel 3: merge (full-width champion, unchanged): out[0] = a + scratch.a,
// out[1] = b + scratch.b (deinterleave). 192 MiB aggregate @ ~8 TB/s: 24us.
// ---------------------------------------------------------------------------
__global__ void __launch_bounds__(256) merge_kernel(
        const float4* __restrict__ a,
        const float4* __restrict__ b,
        float4* __restrict__ out) {
    int i = blockIdx.x * blockDim.x + threadIdx.x;   // [0, ER/4) exact grid
    const float4* s4 = reinterpret_cast<const float4*>(g_scratch);
    float4 p0 = s4[2 * i + 0];   // {a0,b0,a1,b1}
    float4 p1 = s4[2 * i + 1];   // {a2,b2,a3,b3}
    float4 va = __ldcs(a + i);
    float4 vb = __ldcs(b + i);
    __stcs(out + i,
           make_float4(va.x + p0.x, va.y + p0.z, va.z + p1.x, va.w + p1.z));
    __stcs(out + ER / 4 + i,
           make_float4(vb.x + p0.y, vb.y + p0.w, vb.z + p1.y, vb.w + p1.w));
}

extern "C" void kernel_launch(void* const* d_in, const int* in_sizes, int n_in,
                              void* d_out, int out_size) {
    const float* a  = (const float*)d_in[0];          // [E, R]
    const float* b  = (const float*)d_in[1];          // [E, R]
    const int*   sr = (const int*)d_in[2];            // [S, E]
    const float* da = (const float*)d_in[3];          // [S]
    const float* db = (const float*)d_in[4];          // [S]
    float* out = (float*)d_out;                       // [2, E, R]

    // Resolve scratch symbol address once (host-side query, no allocation).
    static char* sp = [] {
        void* p = nullptr;
        cudaGetSymbolAddress(&p, g_scratch);
        return (char*)p;
    }();

    // Phase 1: TMA bulk-store fill of scratch.
    // 64 MiB / 32KB = 2048 CTAs, one bulk store each.
    tma_fill_kernel<<<(int)(sizeof(float) * 2u * ER / FILL_CHUNK), 128>>>(sp);

    // Phase 2: monolithic scatter (12500 blocks exact).
    scatter_v2x4_kernel<<<S_NUM * E_NUM / 4 / 256, 256>>>((const int4*)sr, da, db);

    // Phase 3: merge + deinterleave into output (8192 blocks exact).
    merge_kernel<<<ER / 4 / 256, 256>>>((const float4*)a, (const float4*)b,
                                        (float4*)out);
}